// round 4
// baseline (speedup 1.0000x reference)
#include <cuda_runtime.h>
#include <cuda_fp16.h>
#include <math.h>

#define NB   4
#define CH   16
#define HWSZ 65536
#define EPSV 1e-6f
#define LOG2E_T 14.4269504089f     // (1/TEMP) * log2(e)
#define LN2F    0.69314718056f     // 10 / LOG2E_T

typedef unsigned long long u64;
typedef unsigned int u32;

// Channels-last normalized features in fp16: [n][pix][16 halves] = 8 MB
__device__ u32 g_fnh[(size_t)NB * HWSZ * 8];
__device__ float g_part[1024];
__device__ unsigned int g_ctr = 0;

// ---------------- packed f32x2 helpers ----------------
__device__ __forceinline__ u64 f2mul(u64 a, u64 b) {
    u64 d; asm("mul.rn.f32x2 %0,%1,%2;" : "=l"(d) : "l"(a), "l"(b)); return d;
}
__device__ __forceinline__ u64 f2fma(u64 a, u64 b, u64 c) {
    u64 d; asm("fma.rn.f32x2 %0,%1,%2,%3;" : "=l"(d) : "l"(a), "l"(b), "l"(c)); return d;
}
__device__ __forceinline__ u64 f2add(u64 a, u64 b) {
    u64 d; asm("add.rn.f32x2 %0,%1,%2;" : "=l"(d) : "l"(a), "l"(b)); return d;
}
__device__ __forceinline__ float f2hsum(u64 v) {
    float lo, hi; asm("mov.b64 {%0,%1},%2;" : "=f"(lo), "=f"(hi) : "l"(v));
    return lo + hi;
}
__device__ __forceinline__ u64 pack2(float lo, float hi) {
    u64 d; asm("mov.b64 %0,{%1,%2};" : "=l"(d) : "f"(lo), "f"(hi)); return d;
}
__device__ __forceinline__ float ex2f(float x) {
    float r; asm("ex2.approx.ftz.f32 %0,%1;" : "=f"(r) : "f"(x)); return r;
}
__device__ __forceinline__ float dot16(const u64* a, const u64* b) {
    u64 p = f2mul(a[0], b[0]);
    u64 q = f2mul(a[1], b[1]);
    p = f2fma(a[2], b[2], p);  q = f2fma(a[3], b[3], q);
    p = f2fma(a[4], b[4], p);  q = f2fma(a[5], b[5], q);
    p = f2fma(a[6], b[6], p);  q = f2fma(a[7], b[7], q);
    return f2hsum(f2add(p, q));
}
__device__ __forceinline__ void cvt16(uint4 a, uint4 b, u64 nv[8]) {
    float2 f;
    f = __half22float2(*(const __half2*)&a.x); nv[0] = pack2(f.x, f.y);
    f = __half22float2(*(const __half2*)&a.y); nv[1] = pack2(f.x, f.y);
    f = __half22float2(*(const __half2*)&a.z); nv[2] = pack2(f.x, f.y);
    f = __half22float2(*(const __half2*)&a.w); nv[3] = pack2(f.x, f.y);
    f = __half22float2(*(const __half2*)&b.x); nv[4] = pack2(f.x, f.y);
    f = __half22float2(*(const __half2*)&b.y); nv[5] = pack2(f.x, f.y);
    f = __half22float2(*(const __half2*)&b.z); nv[6] = pack2(f.x, f.y);
    f = __half22float2(*(const __half2*)&b.w); nv[7] = pack2(f.x, f.y);
}
// load 16-half vector from a parity sub-array (idx in [0,127]) with XOR swizzle
__device__ __forceinline__ void loadvec(const char* parityBase, int idx, u64 nv[8]) {
    int sw = ((idx >> 2) & 1) << 4;
    const char* p = parityBase + (idx << 5);
    uint4 a = *(const uint4*)(p + sw);
    uint4 b = *(const uint4*)(p + (16 ^ sw));
    cvt16(a, b, nv);
}

// ---------------------------------------------------------------------------
// Kernel 1: L2-normalize + transpose + fp16 quantize. 4 pixels/thread.
// ---------------------------------------------------------------------------
__global__ void __launch_bounds__(256)
k_norm(const float* __restrict__ f) {
    int idx4 = blockIdx.x * 256 + threadIdx.x;      // 0 .. 65535
    int n    = idx4 >> 14;
    int pix  = (idx4 & 16383) << 2;                 // base pixel (mult of 4)
    const float* base = f + (size_t)n * CH * HWSZ + pix;

    float4 v[CH];
#pragma unroll
    for (int c = 0; c < CH; c++) v[c] = *(const float4*)(base + (size_t)c * HWSZ);

    float s0 = 0.f, s1 = 0.f, s2 = 0.f, s3 = 0.f;
#pragma unroll
    for (int c = 0; c < CH; c++) {
        s0 = fmaf(v[c].x, v[c].x, s0);
        s1 = fmaf(v[c].y, v[c].y, s1);
        s2 = fmaf(v[c].z, v[c].z, s2);
        s3 = fmaf(v[c].w, v[c].w, s3);
    }
    float inv[4];
    inv[0] = 1.f / fmaxf(sqrtf(s0), 1e-12f);
    inv[1] = 1.f / fmaxf(sqrtf(s1), 1e-12f);
    inv[2] = 1.f / fmaxf(sqrtf(s2), 1e-12f);
    inv[3] = 1.f / fmaxf(sqrtf(s3), 1e-12f);

    uint4* o = (uint4*)(g_fnh + (size_t)(n * HWSZ + pix) * 8);
#pragma unroll
    for (int p = 0; p < 4; p++) {
        u32 h[8];
#pragma unroll
        for (int c2 = 0; c2 < 8; c2++) {
            float a = ((const float*)&v[c2*2])[p]     * inv[p];
            float b = ((const float*)&v[c2*2+1])[p]   * inv[p];
            __half2 hh = __floats2half2_rn(a, b);
            h[c2] = *(u32*)&hh;
        }
        o[p*2+0] = make_uint4(h[0], h[1], h[2], h[3]);
        o[p*2+1] = make_uint4(h[4], h[5], h[6], h[7]);
    }
}

// ---------------------------------------------------------------------------
// Fused kernel: even blocks = local 11x11 term (2 rows, 2x2 thread quad),
// odd blocks = directional term. Last-finishing block does the final sum.
// ---------------------------------------------------------------------------
__global__ void __launch_bounds__(128, 2)
k_main(const int* __restrict__ labels, const int* __restrict__ dirs,
       float* __restrict__ out) {
    extern __shared__ char sm[];
    const int bx = blockIdx.x;           // 0..1023
    const int t  = threadIdx.x;          // 0..127
    float val;                           // per-thread partial

    if ((bx & 1) == 0) {
        // ================= LOCAL PART =================
        const int lbx = bx >> 1;         // 0..511
        const int n   = lbx >> 7;
        const int i0  = (lbx & 127) << 1;
        char* sF   = sm;                 // 12 rows * 8192 B (even | odd)
        int*  sLab = (int*)(sm + 98304); // 12 rows * 256 ints

        {
            const uint4* src = (const uint4*)(g_fnh + (size_t)n * HWSZ * 8);
#pragma unroll
            for (int k = 0; k < 48; k++) {
                int lin = t + (k << 7);
                int rr  = lin >> 9;
                int row = i0 - 5 + rr;
                if ((unsigned)row < 256u) {
                    int w = lin & 511;
                    int parity = w >> 8;
                    int idx = w & 255;
                    int e = idx >> 1, ch = idx & 1;
                    int px = (e << 1) + parity;
                    uint4 v = src[(size_t)((row << 8) + px) * 2 + ch];
                    *(uint4*)(sF + (rr << 13) + (parity << 12) + (e << 5)
                              + ((ch ^ ((e >> 2) & 1)) << 4)) = v;
                }
            }
            const int* ls = labels + n * HWSZ;
#pragma unroll
            for (int k = 0; k < 24; k++) {
                int lin = t + (k << 7);
                int rr = lin >> 8;
                int px = lin & 255;
                int row = i0 - 5 + rr;
                int parity = px & 1, e = px >> 1;
                sLab[(rr << 8) + (parity << 7) + e] =
                    ((unsigned)row < 256u) ? ls[(row << 8) + px] : (int)0x80000000;
            }
        }
        __syncthreads();

        // center vectors, pre-scaled by LOG2E_T
        u64 cv00[8], cv01[8], cv10[8], cv11[8];
        loadvec(sF + (5 << 13),        t, cv00);
        loadvec(sF + (5 << 13) + 4096, t, cv01);
        loadvec(sF + (6 << 13),        t, cv10);
        loadvec(sF + (6 << 13) + 4096, t, cv11);
        const u64 kk = pack2(LOG2E_T, LOG2E_T);
#pragma unroll
        for (int c = 0; c < 8; c++) {
            cv00[c] = f2mul(cv00[c], kk);  cv01[c] = f2mul(cv01[c], kk);
            cv10[c] = f2mul(cv10[c], kk);  cv11[c] = f2mul(cv11[c], kk);
        }
        const int clab00 = sLab[(5 << 8) + t];
        const int clab01 = sLab[(5 << 8) + 128 + t];
        const int clab10 = sLab[(6 << 8) + t];
        const int clab11 = sLab[(6 << 8) + 128 + t];

        float S00=0,S01=0,S10=0,S11=0;
        float D00=0,D01=0,D10=0,D11=0;
        int   M00=0,M01=0,M10=0,M11=0;

#pragma unroll 1
        for (int rr = 0; rr < 12; rr++) {
            int row = i0 - 5 + rr;
            if ((unsigned)row >= 256u) continue;   // warp-uniform
            const bool rok0 = (rr <= 10);
            const bool rok1 = (rr >= 1);
            const char* rowE = sF + (rr << 13);
            const char* rowO = rowE + 4096;
            const int* labE = sLab + (rr << 8);
            const int* labO = labE + 128;

            // even-pixel neighbors
#pragma unroll
            for (int u = 0; u < 6; u++) {
                int e = t - 2 + u;
                bool vld = (unsigned)e < 128u;
                int ec = vld ? e : (e < 0 ? 0 : 127);
                u64 nv[8]; loadvec(rowE, ec, nv);
                int lb = labE[ec];
                float dt01 = dot16(cv01, nv);
                float dt11 = dot16(cv11, nv);
                float e01 = ex2f(dt01), e11 = ex2f(dt11);
                bool a0 = vld && rok0 && (lb == clab01);
                bool a1 = vld && rok1 && (lb == clab11);
                if (a0) { S01 += e01; D01 += dt01; M01++; }
                if (a1) { S11 += e11; D11 += dt11; M11++; }
                if (u != 5) {
                    float dt00 = dot16(cv00, nv);
                    float dt10 = dot16(cv10, nv);
                    float e00 = ex2f(dt00), e10 = ex2f(dt10);
                    bool b0 = vld && rok0 && (lb == clab00);
                    bool b1 = vld && rok1 && (lb == clab10);
                    if (b0) { S00 += e00; D00 += dt00; M00++; }
                    if (b1) { S10 += e10; D10 += dt10; M10++; }
                }
            }
            // odd-pixel neighbors
#pragma unroll
            for (int u = 0; u < 6; u++) {
                int m = t - 3 + u;
                bool vld = (unsigned)m < 128u;
                int mc = vld ? m : (m < 0 ? 0 : 127);
                u64 nv[8]; loadvec(rowO, mc, nv);
                int lb = labO[mc];
                float dt00 = dot16(cv00, nv);
                float dt10 = dot16(cv10, nv);
                float e00 = ex2f(dt00), e10 = ex2f(dt10);
                bool b0 = vld && rok0 && (lb == clab00);
                bool b1 = vld && rok1 && (lb == clab10);
                if (b0) { S00 += e00; D00 += dt00; M00++; }
                if (b1) { S10 += e10; D10 += dt10; M10++; }
                if (u != 0) {
                    float dt01 = dot16(cv01, nv);
                    float dt11 = dot16(cv11, nv);
                    float e01 = ex2f(dt01), e11 = ex2f(dt11);
                    bool a0 = vld && rok0 && (lb == clab01);
                    bool a1 = vld && rok1 && (lb == clab11);
                    if (a0) { S01 += e01; D01 += dt01; M01++; }
                    if (a1) { S11 += e11; D11 += dt11; M11++; }
                }
            }
        }

        // contrib = M*ln(S+eps) - ln2 * D'   (D' is log2e*10-scaled dot sum)
        float c00 = fmaf((float)M00, __logf(S00 + EPSV), -LN2F * D00);
        float c01 = fmaf((float)M01, __logf(S01 + EPSV), -LN2F * D01);
        float c10 = fmaf((float)M10, __logf(S10 + EPSV), -LN2F * D10);
        float c11 = fmaf((float)M11, __logf(S11 + EPSV), -LN2F * D11);
        int ci0 = i0, ci1 = i0 + 1, j0 = 2 * t, j1 = 2 * t + 1;
        float ch0 = (float)(11 - max(0, 5 - ci0) - max(0, ci0 - 250));
        float ch1 = (float)(11 - max(0, 5 - ci1) - max(0, ci1 - 250));
        float cw0 = (float)(11 - max(0, 5 - j0)  - max(0, j0  - 250));
        float cw1 = (float)(11 - max(0, 5 - j1)  - max(0, j1  - 250));
        val = (c00 / (ch0 * cw0) + c01 / (ch0 * cw1)
             + c10 / (ch1 * cw0) + c11 / (ch1 * cw1)) * (1.0f / (4.0f * 65536.0f));
    } else {
        // ================= DIRECTIONAL PART =================
        const int dbx = bx >> 1;                    // 0..511
        int tid = dbx * 128 + t;                    // pixel index
        int i = tid >> 8, j = tid & 255;

        int off[NB], lc[NB];
#pragma unroll
        for (int k = 0; k < NB; k++) {
            int di = dirs[(k * 2 + 0) * HWSZ + tid];
            int dj = dirs[(k * 2 + 1) * HWSZ + tid];
            off[k] = ((i + di) << 8) + (j + dj);
            lc[k]  = labels[k * HWSZ + tid];
        }
        const u64 kk = pack2(LOG2E_T, LOG2E_T);

        float sum = 0.f;
#pragma unroll 1
        for (int nn = 0; nn < NB; nn++) {
            const uint4* base = (const uint4*)(g_fnh + (size_t)nn * HWSZ * 8);
            u64 cv[8];
            cvt16(base[(size_t)tid * 2], base[(size_t)tid * 2 + 1], cv);
#pragma unroll
            for (int c = 0; c < 8; c++) cv[c] = f2mul(cv[c], kk);
            float dt[NB]; bool mk[NB]; float S = 0.f;
#pragma unroll
            for (int k = 0; k < NB; k++) {
                u64 nv[8];
                cvt16(base[(size_t)off[k] * 2], base[(size_t)off[k] * 2 + 1], nv);
                dt[k] = dot16(cv, nv);
                mk[k] = (labels[nn * HWSZ + off[k]] == lc[k]);
                S += mk[k] ? ex2f(dt[k]) : 0.f;
            }
            float logS = __logf(S + EPSV);
#pragma unroll
            for (int k = 0; k < NB; k++)
                sum += mk[k] ? (logS - LN2F * dt[k]) : __int_as_float(0x7f800000);
        }
        val = sum * (1.0f / (16.0f * 65536.0f));
    }

    // ---------------- common tail: block reduce + last-block final sum ------
    __shared__ float wred[4];
    __shared__ bool  slast;
#pragma unroll
    for (int o = 16; o > 0; o >>= 1) val += __shfl_down_sync(0xffffffffu, val, o);
    if ((t & 31) == 0) wred[t >> 5] = val;
    __syncthreads();
    if (t == 0) {
        g_part[bx] = (wred[0] + wred[1]) + (wred[2] + wred[3]);
        __threadfence();
        unsigned old = atomicAdd(&g_ctr, 1u);
        slast = (old == 1023u);
    }
    __syncthreads();

    if (slast) {   // deterministic final reduction
        float v = 0.f;
#pragma unroll
        for (int k = 0; k < 8; k++) v += g_part[t + (k << 7)];
#pragma unroll
        for (int o = 16; o > 0; o >>= 1) v += __shfl_down_sync(0xffffffffu, v, o);
        if ((t & 31) == 0) wred[t >> 5] = v;
        __syncthreads();
        if (t == 0) {
            out[0] = (wred[0] + wred[1]) + (wred[2] + wred[3]);
            g_ctr = 0;   // reset for next graph replay
        }
    }
}

// ---------------------------------------------------------------------------
extern "C" void kernel_launch(void* const* d_in, const int* in_sizes, int n_in,
                              void* d_out, int out_size) {
    const float* feat   = (const float*)d_in[0];
    const int*   labels = (const int*)d_in[1];
    const int*   dirs   = (const int*)d_in[2];
    float* out = (float*)d_out;

    const int smem = 98304 + 12288;   // 110,592 B dynamic
    cudaFuncSetAttribute(k_main, cudaFuncAttributeMaxDynamicSharedMemorySize, smem);

    k_norm<<<256, 256>>>(feat);
    k_main<<<1024, 128, smem>>>(labels, dirs, out);
}

// round 5
// speedup vs baseline: 1.2410x; 1.2410x over previous
#include <cuda_runtime.h>
#include <cuda_fp16.h>
#include <math.h>

#define NB   4
#define CH   16
#define HWSZ 65536
#define EPSV 1e-6f
#define LOG2E_T 14.4269504089f     // (1/TEMP) * log2(e)
#define LN2F    0.69314718056f

typedef unsigned long long u64;
typedef unsigned int u32;

// Channels-last normalized features in fp16: [n][pix][16 halves] = 8 MB
__device__ u32 g_fnh[(size_t)NB * HWSZ * 8];
__device__ float g_lp[512];
__device__ float g_dp[256];
__device__ unsigned int g_ctr = 0;

// ---------------- helpers ----------------
__device__ __forceinline__ u64 f2mul(u64 a, u64 b) {
    u64 d; asm("mul.rn.f32x2 %0,%1,%2;" : "=l"(d) : "l"(a), "l"(b)); return d;
}
__device__ __forceinline__ u64 f2fma(u64 a, u64 b, u64 c) {
    u64 d; asm("fma.rn.f32x2 %0,%1,%2,%3;" : "=l"(d) : "l"(a), "l"(b), "l"(c)); return d;
}
__device__ __forceinline__ u64 f2add(u64 a, u64 b) {
    u64 d; asm("add.rn.f32x2 %0,%1,%2;" : "=l"(d) : "l"(a), "l"(b)); return d;
}
__device__ __forceinline__ float f2hsum(u64 v) {
    float lo, hi; asm("mov.b64 {%0,%1},%2;" : "=f"(lo), "=f"(hi) : "l"(v));
    return lo + hi;
}
__device__ __forceinline__ u64 pack2(float lo, float hi) {
    u64 d; asm("mov.b64 %0,{%1,%2};" : "=l"(d) : "f"(lo), "f"(hi)); return d;
}
__device__ __forceinline__ float ex2f(float x) {
    float r; asm("ex2.approx.ftz.f32 %0,%1;" : "=f"(r) : "f"(x)); return r;
}
// fp32x2 dot (used by k_dir)
__device__ __forceinline__ float dot16(const u64* a, const u64* b) {
    u64 p = f2mul(a[0], b[0]);
    u64 q = f2mul(a[1], b[1]);
    p = f2fma(a[2], b[2], p);  q = f2fma(a[3], b[3], q);
    p = f2fma(a[4], b[4], p);  q = f2fma(a[5], b[5], q);
    p = f2fma(a[6], b[6], p);  q = f2fma(a[7], b[7], q);
    return f2hsum(f2add(p, q));
}
__device__ __forceinline__ void cvt16(uint4 a, uint4 b, u64 nv[8]) {
    float2 f;
    f = __half22float2(*(const __half2*)&a.x); nv[0] = pack2(f.x, f.y);
    f = __half22float2(*(const __half2*)&a.y); nv[1] = pack2(f.x, f.y);
    f = __half22float2(*(const __half2*)&a.z); nv[2] = pack2(f.x, f.y);
    f = __half22float2(*(const __half2*)&a.w); nv[3] = pack2(f.x, f.y);
    f = __half22float2(*(const __half2*)&b.x); nv[4] = pack2(f.x, f.y);
    f = __half22float2(*(const __half2*)&b.y); nv[5] = pack2(f.x, f.y);
    f = __half22float2(*(const __half2*)&b.z); nv[6] = pack2(f.x, f.y);
    f = __half22float2(*(const __half2*)&b.w); nv[7] = pack2(f.x, f.y);
}

// ---- fp16 (half2) 16-dim dot: 8 HFMA2 in 2 chains, join, fold, 1 convert ----
__device__ __forceinline__ float dot16h(const u32 a[8], const u32 b[8]) {
    u32 p, q, r, rs, r2;
    asm("mul.rn.f16x2 %0,%1,%2;" : "=r"(p) : "r"(a[0]), "r"(b[0]));
    asm("mul.rn.f16x2 %0,%1,%2;" : "=r"(q) : "r"(a[1]), "r"(b[1]));
    asm("fma.rn.f16x2 %0,%1,%2,%3;" : "=r"(p) : "r"(a[2]), "r"(b[2]), "r"(p));
    asm("fma.rn.f16x2 %0,%1,%2,%3;" : "=r"(q) : "r"(a[3]), "r"(b[3]), "r"(q));
    asm("fma.rn.f16x2 %0,%1,%2,%3;" : "=r"(p) : "r"(a[4]), "r"(b[4]), "r"(p));
    asm("fma.rn.f16x2 %0,%1,%2,%3;" : "=r"(q) : "r"(a[5]), "r"(b[5]), "r"(q));
    asm("fma.rn.f16x2 %0,%1,%2,%3;" : "=r"(p) : "r"(a[6]), "r"(b[6]), "r"(p));
    asm("fma.rn.f16x2 %0,%1,%2,%3;" : "=r"(q) : "r"(a[7]), "r"(b[7]), "r"(q));
    asm("add.rn.f16x2 %0,%1,%2;" : "=r"(r) : "r"(p), "r"(q));
    asm("prmt.b32 %0,%1,%1,0x1032;" : "=r"(rs) : "r"(r));
    asm("add.rn.f16x2 %0,%1,%2;" : "=r"(r2) : "r"(r), "r"(rs));
    float f;
    asm("{.reg .b16 lo,hi; mov.b32 {lo,hi}, %1; cvt.f32.f16 %0, lo;}"
        : "=f"(f) : "r"(r2));
    return f;
}
// load 16 halves (as 8 u32) from a parity sub-array with XOR swizzle
__device__ __forceinline__ void load16h(const char* base, int idx, u32 h[8]) {
    int sw = ((idx >> 2) & 1) << 4;
    const char* p = base + (idx << 5);
    uint4 a = *(const uint4*)(p + sw);
    uint4 b = *(const uint4*)(p + (16 ^ sw));
    h[0]=a.x; h[1]=a.y; h[2]=a.z; h[3]=a.w;
    h[4]=b.x; h[5]=b.y; h[6]=b.z; h[7]=b.w;
}

// ---------------------------------------------------------------------------
// Kernel 1: L2-normalize + transpose + fp16 quantize. 4 pixels/thread.
// ---------------------------------------------------------------------------
__global__ void __launch_bounds__(256)
k_norm(const float* __restrict__ f) {
    int idx4 = blockIdx.x * 256 + threadIdx.x;      // 0 .. 65535
    int n    = idx4 >> 14;
    int pix  = (idx4 & 16383) << 2;
    const float* base = f + (size_t)n * CH * HWSZ + pix;

    float4 v[CH];
#pragma unroll
    for (int c = 0; c < CH; c++) v[c] = *(const float4*)(base + (size_t)c * HWSZ);

    float s0 = 0.f, s1 = 0.f, s2 = 0.f, s3 = 0.f;
#pragma unroll
    for (int c = 0; c < CH; c++) {
        s0 = fmaf(v[c].x, v[c].x, s0);
        s1 = fmaf(v[c].y, v[c].y, s1);
        s2 = fmaf(v[c].z, v[c].z, s2);
        s3 = fmaf(v[c].w, v[c].w, s3);
    }
    float inv[4];
    inv[0] = 1.f / fmaxf(sqrtf(s0), 1e-12f);
    inv[1] = 1.f / fmaxf(sqrtf(s1), 1e-12f);
    inv[2] = 1.f / fmaxf(sqrtf(s2), 1e-12f);
    inv[3] = 1.f / fmaxf(sqrtf(s3), 1e-12f);

    uint4* o = (uint4*)(g_fnh + (size_t)(n * HWSZ + pix) * 8);
#pragma unroll
    for (int p = 0; p < 4; p++) {
        u32 h[8];
#pragma unroll
        for (int c2 = 0; c2 < 8; c2++) {
            float a = ((const float*)&v[c2*2])[p]   * inv[p];
            float b = ((const float*)&v[c2*2+1])[p] * inv[p];
            __half2 hh = __floats2half2_rn(a, b);
            h[c2] = *(u32*)&hh;
        }
        o[p*2+0] = make_uint4(h[0], h[1], h[2], h[3]);
        o[p*2+1] = make_uint4(h[4], h[5], h[6], h[7]);
    }
}

// ---------------------------------------------------------------------------
// Kernel 2: local 11x11 term. Block = (n, 4 center rows, 128-col half).
// 128 threads; thread t owns 2x2 quad: rows i0+2rq, i0+2rq+1 (rq=t>>6),
// cols cb+8+2c, +1 (c=t&63).  Halo tile = 14 rows x 144 cols, fp16
// channels-last, even/odd parity split + XOR swizzle. 3 blocks/SM.
// ---------------------------------------------------------------------------
#define ROWB 4608                    // bytes per row slot (72+72 vecs of 32B)
__global__ void __launch_bounds__(128, 3)
k_local(const int* __restrict__ labels) {
    extern __shared__ char sm[];
    char* sF   = sm;                      // 14 * 4608 = 64512 B
    int*  sLab = (int*)(sm + 14 * ROWB);  // 14 * 144 ints = 8064 B

    const int bx  = blockIdx.x;           // 0..511
    const int n   = bx >> 7;
    const int rem = bx & 127;
    const int i0  = (rem >> 1) << 2;      // first center row (mult of 4)
    const int hB  = rem & 1;              // which 128-col half
    const int cb  = hB * 128 - 8;         // tile base col (global)
    const int t   = threadIdx.x;

    // ---- fill halo: 14 rows x 144 cols ----
    {
        const uint4* src = (const uint4*)(g_fnh + (size_t)n * HWSZ * 8);
#pragma unroll
        for (int k = 0; k < 32; k++) {
            int lin = t + (k << 7);           // 0..4095 (need 4032)
            if (lin < 4032) {
                int rr = lin / 288;           // row slot
                int w  = lin - rr * 288;
                int ch = w & 1;
                int x  = w >> 1;              // tile col 0..143
                int row = i0 - 5 + rr;
                int g   = cb + x;
                if ((unsigned)row < 256u && (unsigned)g < 256u) {
                    uint4 v = src[(size_t)((row << 8) + g) * 2 + ch];
                    int parity = x & 1, e = x >> 1;
                    *(uint4*)(sF + rr * ROWB + parity * 2304 + (e << 5)
                              + ((ch ^ ((e >> 2) & 1)) << 4)) = v;
                }
            }
        }
        const int* ls = labels + n * HWSZ;
#pragma unroll
        for (int k = 0; k < 16; k++) {
            int lin = t + (k << 7);           // 0..2047 (need 2016)
            if (lin < 2016) {
                int rr = lin / 144;
                int x  = lin - rr * 144;
                int row = i0 - 5 + rr;
                int g   = cb + x;
                bool ok = ((unsigned)row < 256u) && ((unsigned)g < 256u);
                sLab[rr * 144 + (x & 1) * 72 + (x >> 1)] =
                    ok ? ls[(row << 8) + g] : (int)0x80000000;
            }
        }
    }
    __syncthreads();

    const int rq = t >> 6;               // 0/1 (warp-uniform)
    const int c  = t & 63;
    const int tc = c + 4;                // center parity index
    const int sA = 2 * rq + 5;           // slot of center row A
    const int sB = sA + 1;

    u32 cvAe[8], cvAo[8], cvBe[8], cvBo[8];
    load16h(sF + sA * ROWB,        tc, cvAe);
    load16h(sF + sA * ROWB + 2304, tc, cvAo);
    load16h(sF + sB * ROWB,        tc, cvBe);
    load16h(sF + sB * ROWB + 2304, tc, cvBo);
    const int clAe = sLab[sA * 144 + tc];
    const int clAo = sLab[sA * 144 + 72 + tc];
    const int clBe = sLab[sB * 144 + tc];
    const int clBo = sLab[sB * 144 + 72 + tc];

    float SAe=0,SAo=0,SBe=0,SBo=0;
    float DAe=0,DAo=0,DBe=0,DBo=0;
    int   MAe=0,MAo=0,MBe=0,MBo=0;

#pragma unroll 1
    for (int v = 0; v < 12; v++) {
        int s   = 2 * rq + v;
        int row = i0 - 5 + s;
        if ((unsigned)row >= 256u) continue;   // warp-uniform
        const bool rokA = (v <= 10);
        const bool rokB = (v >= 1);
        const char* rowE = sF + s * ROWB;
        const char* rowO = rowE + 2304;
        const int* labE = sLab + s * 144;
        const int* labO = labE + 72;

        // even-pixel neighbors: e = c+2+u; odd centers all u, even centers u<5
#pragma unroll
        for (int u = 0; u < 6; u++) {
            int e  = c + 2 + u;
            int gx = cb + (e << 1);
            bool vld = (unsigned)gx < 256u;
            u32 nv[8]; load16h(rowE, e, nv);
            int lb = labE[e];
            {
                float dAo = dot16h(cvAo, nv) * LOG2E_T;
                float dBo = dot16h(cvBo, nv) * LOG2E_T;
                float eA = ex2f(dAo), eB = ex2f(dBo);
                if (vld && rokA && lb == clAo) { SAo += eA; DAo += dAo; MAo++; }
                if (vld && rokB && lb == clBo) { SBo += eB; DBo += dBo; MBo++; }
            }
            if (u != 5) {
                float dAe = dot16h(cvAe, nv) * LOG2E_T;
                float dBe = dot16h(cvBe, nv) * LOG2E_T;
                float eA = ex2f(dAe), eB = ex2f(dBe);
                if (vld && rokA && lb == clAe) { SAe += eA; DAe += dAe; MAe++; }
                if (vld && rokB && lb == clBe) { SBe += eB; DBe += dBe; MBe++; }
            }
        }
        // odd-pixel neighbors: o = c+1+u; even centers all u, odd centers u>0
#pragma unroll
        for (int u = 0; u < 6; u++) {
            int o  = c + 1 + u;
            int gx = cb + (o << 1) + 1;
            bool vld = (unsigned)gx < 256u;
            u32 nv[8]; load16h(rowO, o, nv);
            int lb = labO[o];
            {
                float dAe = dot16h(cvAe, nv) * LOG2E_T;
                float dBe = dot16h(cvBe, nv) * LOG2E_T;
                float eA = ex2f(dAe), eB = ex2f(dBe);
                if (vld && rokA && lb == clAe) { SAe += eA; DAe += dAe; MAe++; }
                if (vld && rokB && lb == clBe) { SBe += eB; DBe += dBe; MBe++; }
            }
            if (u != 0) {
                float dAo = dot16h(cvAo, nv) * LOG2E_T;
                float dBo = dot16h(cvBo, nv) * LOG2E_T;
                float eA = ex2f(dAo), eB = ex2f(dBo);
                if (vld && rokA && lb == clAo) { SAo += eA; DAo += dAo; MAo++; }
                if (vld && rokB && lb == clBo) { SBo += eB; DBo += dBo; MBo++; }
            }
        }
    }

    // contrib = M*ln(S+eps) - ln2 * D  (D is log2-scaled logit sum)
    float cAe = fmaf((float)MAe, __logf(SAe + EPSV), -LN2F * DAe);
    float cAo = fmaf((float)MAo, __logf(SAo + EPSV), -LN2F * DAo);
    float cBe = fmaf((float)MBe, __logf(SBe + EPSV), -LN2F * DBe);
    float cBo = fmaf((float)MBo, __logf(SBo + EPSV), -LN2F * DBo);
    int ciA = i0 + 2 * rq, ciB = ciA + 1;
    int j0  = hB * 128 + 2 * c, j1 = j0 + 1;
    float chA = (float)(11 - max(0, 5 - ciA) - max(0, ciA - 250));
    float chB = (float)(11 - max(0, 5 - ciB) - max(0, ciB - 250));
    float cw0 = (float)(11 - max(0, 5 - j0)  - max(0, j0  - 250));
    float cw1 = (float)(11 - max(0, 5 - j1)  - max(0, j1  - 250));
    float val = (cAe / (chA * cw0) + cAo / (chA * cw1)
               + cBe / (chB * cw0) + cBo / (chB * cw1)) * (1.0f / (4.0f * 65536.0f));

    // deterministic block reduction
    __shared__ float wred[4];
#pragma unroll
    for (int o = 16; o > 0; o >>= 1) val += __shfl_down_sync(0xffffffffu, val, o);
    if ((t & 31) == 0) wred[t >> 5] = val;
    __syncthreads();
    if (t == 0) g_lp[bx] = (wred[0] + wred[1]) + (wred[2] + wred[3]);
}

// ---------------------------------------------------------------------------
// Kernel 3: directional term + folded final reduction (last-block pattern).
// ---------------------------------------------------------------------------
__global__ void __launch_bounds__(256)
k_dir(const int* __restrict__ labels, const int* __restrict__ dirs,
      float* __restrict__ out) {
    int tid = blockIdx.x * 256 + threadIdx.x;   // pixel index i*256+j
    int i = tid >> 8, j = tid & 255;
    int t = threadIdx.x;

    int off[NB], lc[NB];
#pragma unroll
    for (int k = 0; k < NB; k++) {
        int di = dirs[(k * 2 + 0) * HWSZ + tid];
        int dj = dirs[(k * 2 + 1) * HWSZ + tid];
        off[k] = ((i + di) << 8) + (j + dj);
        lc[k]  = labels[k * HWSZ + tid];
    }
    const u64 kk = pack2(LOG2E_T, LOG2E_T);

    float sum = 0.f;
#pragma unroll 1
    for (int nn = 0; nn < NB; nn++) {
        const uint4* base = (const uint4*)(g_fnh + (size_t)nn * HWSZ * 8);
        u64 cv[8];
        cvt16(base[(size_t)tid * 2], base[(size_t)tid * 2 + 1], cv);
#pragma unroll
        for (int c = 0; c < 8; c++) cv[c] = f2mul(cv[c], kk);
        float dt[NB]; bool mk[NB]; float S = 0.f;
#pragma unroll
        for (int k = 0; k < NB; k++) {
            u64 nv[8];
            cvt16(base[(size_t)off[k] * 2], base[(size_t)off[k] * 2 + 1], nv);
            dt[k] = dot16(cv, nv);
            mk[k] = (labels[nn * HWSZ + off[k]] == lc[k]);
            S += mk[k] ? ex2f(dt[k]) : 0.f;
        }
        float logS = __logf(S + EPSV);
#pragma unroll
        for (int k = 0; k < NB; k++)
            sum += mk[k] ? (logS - LN2F * dt[k]) : __int_as_float(0x7f800000);
    }
    float val = sum * (1.0f / (16.0f * 65536.0f));

    // block reduce (deterministic), last-finishing block folds the final sum
    __shared__ float wred[8];
    __shared__ bool  slast;
#pragma unroll
    for (int o = 16; o > 0; o >>= 1) val += __shfl_down_sync(0xffffffffu, val, o);
    if ((t & 31) == 0) wred[t >> 5] = val;
    __syncthreads();
    if (t < 32) {
        float x = (t < 8) ? wred[t] : 0.f;
#pragma unroll
        for (int o = 4; o > 0; o >>= 1) x += __shfl_down_sync(0xffffffffu, x, o);
        if (t == 0) {
            g_dp[blockIdx.x] = x;
            __threadfence();
            unsigned old = atomicAdd(&g_ctr, 1u);
            slast = (old == 255u);
        }
    }
    __syncthreads();

    if (slast) {
        float v = g_lp[t] + g_lp[t + 256] + g_dp[t];
#pragma unroll
        for (int o = 16; o > 0; o >>= 1) v += __shfl_down_sync(0xffffffffu, v, o);
        if ((t & 31) == 0) wred[t >> 5] = v;
        __syncthreads();
        if (t == 0) {
            float s = 0.f;
#pragma unroll
            for (int w = 0; w < 8; w++) s += wred[w];
            out[0] = s;
            g_ctr = 0;   // reset for next graph replay
        }
    }
}

// ---------------------------------------------------------------------------
extern "C" void kernel_launch(void* const* d_in, const int* in_sizes, int n_in,
                              void* d_out, int out_size) {
    const float* feat   = (const float*)d_in[0];
    const int*   labels = (const int*)d_in[1];
    const int*   dirs   = (const int*)d_in[2];
    float* out = (float*)d_out;

    const int smem = 14 * ROWB + 14 * 144 * 4;   // 64512 + 8064 = 72576 B
    cudaFuncSetAttribute(k_local, cudaFuncAttributeMaxDynamicSharedMemorySize, smem);

    k_norm<<<256, 256>>>(feat);
    k_local<<<512, 128, smem>>>(labels);
    k_dir<<<256, 256>>>(labels, dirs, out);
}

// round 7
// speedup vs baseline: 1.2504x; 1.0075x over previous
#include <cuda_runtime.h>
#include <cuda_fp16.h>
#include <math.h>

#define NB   4
#define CH   16
#define HWSZ 65536
#define EPSV 1e-6f
#define LOG2E_T 14.4269504089f     // (1/TEMP) * log2(e)
#define LN2F    0.69314718056f

typedef unsigned long long u64;
typedef unsigned int u32;

// Channels-last normalized features in fp16: [n][pix][16 halves] = 8 MB
__device__ u32 g_fnh[(size_t)NB * HWSZ * 8];
__device__ float g_lp[512];
__device__ float g_dp[1024];
__device__ unsigned int g_ctr = 0;

// ---------------- helpers ----------------
__device__ __forceinline__ u64 f2add(u64 a, u64 b) {
    u64 d; asm("add.rn.f32x2 %0,%1,%2;" : "=l"(d) : "l"(a), "l"(b)); return d;
}
__device__ __forceinline__ u64 pack2(float lo, float hi) {
    u64 d; asm("mov.b64 %0,{%1,%2};" : "=l"(d) : "f"(lo), "f"(hi)); return d;
}
__device__ __forceinline__ void unpack2(u64 v, float& lo, float& hi) {
    asm("mov.b64 {%0,%1},%2;" : "=f"(lo), "=f"(hi) : "l"(v));
}
__device__ __forceinline__ float ex2f(float x) {
    float r; asm("ex2.approx.ftz.f32 %0,%1;" : "=f"(r) : "f"(x)); return r;
}
// fp16 (half2) 16-dim dot: 8 HFMA2 in 2 chains, join, fold, 1 convert
__device__ __forceinline__ float dot16h(const u32 a[8], const u32 b[8]) {
    u32 p, q, r, rs, r2;
    asm("mul.rn.f16x2 %0,%1,%2;" : "=r"(p) : "r"(a[0]), "r"(b[0]));
    asm("mul.rn.f16x2 %0,%1,%2;" : "=r"(q) : "r"(a[1]), "r"(b[1]));
    asm("fma.rn.f16x2 %0,%1,%2,%3;" : "=r"(p) : "r"(a[2]), "r"(b[2]), "r"(p));
    asm("fma.rn.f16x2 %0,%1,%2,%3;" : "=r"(q) : "r"(a[3]), "r"(b[3]), "r"(q));
    asm("fma.rn.f16x2 %0,%1,%2,%3;" : "=r"(p) : "r"(a[4]), "r"(b[4]), "r"(p));
    asm("fma.rn.f16x2 %0,%1,%2,%3;" : "=r"(q) : "r"(a[5]), "r"(b[5]), "r"(q));
    asm("fma.rn.f16x2 %0,%1,%2,%3;" : "=r"(p) : "r"(a[6]), "r"(b[6]), "r"(p));
    asm("fma.rn.f16x2 %0,%1,%2,%3;" : "=r"(q) : "r"(a[7]), "r"(b[7]), "r"(q));
    asm("add.rn.f16x2 %0,%1,%2;" : "=r"(r) : "r"(p), "r"(q));
    asm("prmt.b32 %0,%1,%1,0x1032;" : "=r"(rs) : "r"(r));
    asm("add.rn.f16x2 %0,%1,%2;" : "=r"(r2) : "r"(r), "r"(rs));
    float f;
    asm("{.reg .b16 lo,hi; mov.b32 {lo,hi}, %1; cvt.f32.f16 %0, lo;}"
        : "=f"(f) : "r"(r2));
    return f;
}
// scale 8 half2 regs by splat constant (fp16)
__device__ __forceinline__ void scale16h(u32 h[8], u32 k2) {
#pragma unroll
    for (int i = 0; i < 8; i++)
        asm("mul.rn.f16x2 %0,%1,%2;" : "=r"(h[i]) : "r"(h[i]), "r"(k2));
}
// load 16 halves (as 8 u32) from a parity sub-array with XOR swizzle
__device__ __forceinline__ void load16h(const char* base, int idx, u32 h[8]) {
    int sw = ((idx >> 2) & 1) << 4;
    const char* p = base + (idx << 5);
    uint4 a = *(const uint4*)(p + sw);
    uint4 b = *(const uint4*)(p + (16 ^ sw));
    h[0]=a.x; h[1]=a.y; h[2]=a.z; h[3]=a.w;
    h[4]=b.x; h[5]=b.y; h[6]=b.z; h[7]=b.w;
}

// ---------------------------------------------------------------------------
// Kernel 1: L2-normalize + transpose + fp16 quantize. 2 pixels/thread.
// ---------------------------------------------------------------------------
__global__ void __launch_bounds__(256)
k_norm(const float* __restrict__ f) {
    int idx2 = blockIdx.x * 256 + threadIdx.x;      // 0 .. 131071
    int n    = idx2 >> 15;
    int pix  = (idx2 & 32767) << 1;
    const float* base = f + (size_t)n * CH * HWSZ + pix;

    float2 v[CH];
#pragma unroll
    for (int c = 0; c < CH; c++) v[c] = *(const float2*)(base + (size_t)c * HWSZ);

    float s0 = 0.f, s1 = 0.f;
#pragma unroll
    for (int c = 0; c < CH; c++) {
        s0 = fmaf(v[c].x, v[c].x, s0);
        s1 = fmaf(v[c].y, v[c].y, s1);
    }
    float i0 = 1.f / fmaxf(sqrtf(s0), 1e-12f);
    float i1 = 1.f / fmaxf(sqrtf(s1), 1e-12f);

    uint4* o = (uint4*)(g_fnh + (size_t)(n * HWSZ + pix) * 8);
    u32 h0[8], h1[8];
#pragma unroll
    for (int c2 = 0; c2 < 8; c2++) {
        __half2 a = __floats2half2_rn(v[c2*2].x * i0, v[c2*2+1].x * i0);
        __half2 b = __floats2half2_rn(v[c2*2].y * i1, v[c2*2+1].y * i1);
        h0[c2] = *(u32*)&a;
        h1[c2] = *(u32*)&b;
    }
    o[0] = make_uint4(h0[0], h0[1], h0[2], h0[3]);
    o[1] = make_uint4(h0[4], h0[5], h0[6], h0[7]);
    o[2] = make_uint4(h1[0], h1[1], h1[2], h1[3]);
    o[3] = make_uint4(h1[4], h1[5], h1[6], h1[7]);
}

// ---------------------------------------------------------------------------
// Kernel 2: local 11x11 term. Block = (n, 4 center rows, 128-col half).
// 128 threads, 2x2 quad per thread. Center vectors pre-scaled by
// 10*log2(e) in fp16; S/D accumulated as one packed f32x2 add.
// ---------------------------------------------------------------------------
#define ROWB 4608                    // bytes per row slot (72+72 vecs of 32B)
__global__ void __launch_bounds__(128, 3)
k_local(const int* __restrict__ labels) {
    extern __shared__ char sm[];
    char* sF   = sm;                      // 14 * 4608 = 64512 B
    int*  sLab = (int*)(sm + 14 * ROWB);  // 14 * 144 ints = 8064 B

    const int bx  = blockIdx.x;           // 0..511
    const int n   = bx >> 7;
    const int rem = bx & 127;
    const int i0  = (rem >> 1) << 2;      // first center row (mult of 4)
    const int hB  = rem & 1;              // which 128-col half
    const int cb  = hB * 128 - 8;         // tile base col (global)
    const int t   = threadIdx.x;

    // ---- fill halo: 14 rows x 144 cols ----
    {
        const uint4* src = (const uint4*)(g_fnh + (size_t)n * HWSZ * 8);
#pragma unroll
        for (int k = 0; k < 32; k++) {
            int lin = t + (k << 7);           // need 4032
            if (lin < 4032) {
                int rr = lin / 288;
                int w  = lin - rr * 288;
                int ch = w & 1;
                int x  = w >> 1;              // tile col 0..143
                int row = i0 - 5 + rr;
                int g   = cb + x;
                if ((unsigned)row < 256u && (unsigned)g < 256u) {
                    uint4 v = src[(size_t)((row << 8) + g) * 2 + ch];
                    int parity = x & 1, e = x >> 1;
                    *(uint4*)(sF + rr * ROWB + parity * 2304 + (e << 5)
                              + ((ch ^ ((e >> 2) & 1)) << 4)) = v;
                }
            }
        }
        const int* ls = labels + n * HWSZ;
#pragma unroll
        for (int k = 0; k < 16; k++) {
            int lin = t + (k << 7);           // need 2016
            if (lin < 2016) {
                int rr = lin / 144;
                int x  = lin - rr * 144;
                int row = i0 - 5 + rr;
                int g   = cb + x;
                bool ok = ((unsigned)row < 256u) && ((unsigned)g < 256u);
                sLab[rr * 144 + (x & 1) * 72 + (x >> 1)] =
                    ok ? ls[(row << 8) + g] : (int)0x80000000;
            }
        }
    }
    __syncthreads();

    const int rq = t >> 6;               // 0/1 (warp-uniform)
    const int c  = t & 63;
    const int tc = c + 4;
    const int sA = 2 * rq + 5;
    const int sB = sA + 1;

    u32 cvAe[8], cvAo[8], cvBe[8], cvBo[8];
    load16h(sF + sA * ROWB,        tc, cvAe);
    load16h(sF + sA * ROWB + 2304, tc, cvAo);
    load16h(sF + sB * ROWB,        tc, cvBe);
    load16h(sF + sB * ROWB + 2304, tc, cvBo);
    __half2 kt = __floats2half2_rn(LOG2E_T, LOG2E_T);
    u32 kt2 = *(u32*)&kt;
    scale16h(cvAe, kt2); scale16h(cvAo, kt2);
    scale16h(cvBe, kt2); scale16h(cvBo, kt2);
    const int clAe = sLab[sA * 144 + tc];
    const int clAo = sLab[sA * 144 + 72 + tc];
    const int clBe = sLab[sB * 144 + tc];
    const int clBo = sLab[sB * 144 + 72 + tc];

    u64 SDAe = 0, SDAo = 0, SDBe = 0, SDBo = 0;   // packed {S, D}
    int MAe = 0, MAo = 0, MBe = 0, MBo = 0;

#pragma unroll 1
    for (int v = 0; v < 12; v++) {
        int s   = 2 * rq + v;
        int row = i0 - 5 + s;
        if ((unsigned)row >= 256u) continue;   // warp-uniform
        const bool rokA = (v <= 10);
        const bool rokB = (v >= 1);
        const char* rowE = sF + s * ROWB;
        const char* rowO = rowE + 2304;
        const int* labE = sLab + s * 144;
        const int* labO = labE + 72;

        // even-pixel neighbors
#pragma unroll
        for (int u = 0; u < 6; u++) {
            int e  = c + 2 + u;
            int gx = cb + (e << 1);
            bool vld = (unsigned)gx < 256u;
            u32 nv[8]; load16h(rowE, e, nv);
            int lb = labE[e];
            {
                float dAo = dot16h(cvAo, nv);      // already log2-scaled
                float dBo = dot16h(cvBo, nv);
                float eA = ex2f(dAo), eB = ex2f(dBo);
                if (vld && rokA && lb == clAo) { SDAo = f2add(SDAo, pack2(eA, dAo)); MAo++; }
                if (vld && rokB && lb == clBo) { SDBo = f2add(SDBo, pack2(eB, dBo)); MBo++; }
            }
            if (u != 5) {
                float dAe = dot16h(cvAe, nv);
                float dBe = dot16h(cvBe, nv);
                float eA = ex2f(dAe), eB = ex2f(dBe);
                if (vld && rokA && lb == clAe) { SDAe = f2add(SDAe, pack2(eA, dAe)); MAe++; }
                if (vld && rokB && lb == clBe) { SDBe = f2add(SDBe, pack2(eB, dBe)); MBe++; }
            }
        }
        // odd-pixel neighbors
#pragma unroll
        for (int u = 0; u < 6; u++) {
            int o  = c + 1 + u;
            int gx = cb + (o << 1) + 1;
            bool vld = (unsigned)gx < 256u;
            u32 nv[8]; load16h(rowO, o, nv);
            int lb = labO[o];
            {
                float dAe = dot16h(cvAe, nv);
                float dBe = dot16h(cvBe, nv);
                float eA = ex2f(dAe), eB = ex2f(dBe);
                if (vld && rokA && lb == clAe) { SDAe = f2add(SDAe, pack2(eA, dAe)); MAe++; }
                if (vld && rokB && lb == clBe) { SDBe = f2add(SDBe, pack2(eB, dBe)); MBe++; }
            }
            if (u != 0) {
                float dAo = dot16h(cvAo, nv);
                float dBo = dot16h(cvBo, nv);
                float eA = ex2f(dAo), eB = ex2f(dBo);
                if (vld && rokA && lb == clAo) { SDAo = f2add(SDAo, pack2(eA, dAo)); MAo++; }
                if (vld && rokB && lb == clBo) { SDBo = f2add(SDBo, pack2(eB, dBo)); MBo++; }
            }
        }
    }

    float SAe, DAe, SAo, DAo, SBe, DBe, SBo, DBo;
    unpack2(SDAe, SAe, DAe);  unpack2(SDAo, SAo, DAo);
    unpack2(SDBe, SBe, DBe);  unpack2(SDBo, SBo, DBo);

    float cAe = fmaf((float)MAe, __logf(SAe + EPSV), -LN2F * DAe);
    float cAo = fmaf((float)MAo, __logf(SAo + EPSV), -LN2F * DAo);
    float cBe = fmaf((float)MBe, __logf(SBe + EPSV), -LN2F * DBe);
    float cBo = fmaf((float)MBo, __logf(SBo + EPSV), -LN2F * DBo);
    int ciA = i0 + 2 * rq, ciB = ciA + 1;
    int j0  = hB * 128 + 2 * c, j1 = j0 + 1;
    float chA = (float)(11 - max(0, 5 - ciA) - max(0, ciA - 250));
    float chB = (float)(11 - max(0, 5 - ciB) - max(0, ciB - 250));
    float cw0 = (float)(11 - max(0, 5 - j0)  - max(0, j0  - 250));
    float cw1 = (float)(11 - max(0, 5 - j1)  - max(0, j1  - 250));
    float val = (cAe / (chA * cw0) + cAo / (chA * cw1)
               + cBe / (chB * cw0) + cBo / (chB * cw1)) * (1.0f / (4.0f * 65536.0f));

    __shared__ float wred[4];
#pragma unroll
    for (int o = 16; o > 0; o >>= 1) val += __shfl_down_sync(0xffffffffu, val, o);
    if ((t & 31) == 0) wred[t >> 5] = val;
    __syncthreads();
    if (t == 0) g_lp[bx] = (wred[0] + wred[1]) + (wred[2] + wred[3]);
}

// ---------------------------------------------------------------------------
// Kernel 3: directional term, one n per 256-block slice (grid 1024) + final
// folded reduction in the last-finishing block.
// ---------------------------------------------------------------------------
__global__ void __launch_bounds__(256)
k_dir(const int* __restrict__ labels, const int* __restrict__ dirs,
      float* __restrict__ out) {
    const int bx = blockIdx.x;                  // 0..1023
    const int t  = threadIdx.x;
    const int nn  = bx >> 8;                    // batch of the features
    const int pix = ((bx & 255) << 8) + t;      // pixel index i*256+j
    const int i = pix >> 8, j = pix & 255;

    // direction field k applied to features of batch nn; center label from
    // batch k (reference: mask[n,k] = labels[k,i,j] == labels[n,ni_k,nj_k])
    int off[NB], lc[NB];
#pragma unroll
    for (int k = 0; k < NB; k++) {
        int dik = dirs[(k * 2 + 0) * HWSZ + pix];
        int djk = dirs[(k * 2 + 1) * HWSZ + pix];
        off[k] = ((i + dik) << 8) + (j + djk);
        lc[k]  = labels[k * HWSZ + pix];
    }

    const uint4* base = (const uint4*)(g_fnh + (size_t)nn * HWSZ * 8);
    u32 cv[8];
    {
        uint4 a = base[(size_t)pix * 2], b = base[(size_t)pix * 2 + 1];
        cv[0]=a.x; cv[1]=a.y; cv[2]=a.z; cv[3]=a.w;
        cv[4]=b.x; cv[5]=b.y; cv[6]=b.z; cv[7]=b.w;
    }
    __half2 kt = __floats2half2_rn(LOG2E_T, LOG2E_T);
    scale16h(cv, *(u32*)&kt);

    float dt[NB]; bool mk[NB]; float S = 0.f;
#pragma unroll
    for (int k = 0; k < NB; k++) {
        u32 nv[8];
        uint4 a = base[(size_t)off[k] * 2], b = base[(size_t)off[k] * 2 + 1];
        nv[0]=a.x; nv[1]=a.y; nv[2]=a.z; nv[3]=a.w;
        nv[4]=b.x; nv[5]=b.y; nv[6]=b.z; nv[7]=b.w;
        dt[k] = dot16h(cv, nv);                 // log2-scaled logit
        mk[k] = (labels[nn * HWSZ + off[k]] == lc[k]);
        S += mk[k] ? ex2f(dt[k]) : 0.f;
    }
    float logS = __logf(S + EPSV);
    float sum = 0.f;
#pragma unroll
    for (int k = 0; k < NB; k++)
        sum += mk[k] ? (logS - LN2F * dt[k]) : __int_as_float(0x7f800000);
    float val = sum * (1.0f / (16.0f * 65536.0f));

    // block reduce (deterministic), last-finishing block folds the final sum
    __shared__ float wred[8];
    __shared__ bool  slast;
#pragma unroll
    for (int o = 16; o > 0; o >>= 1) val += __shfl_down_sync(0xffffffffu, val, o);
    if ((t & 31) == 0) wred[t >> 5] = val;
    __syncthreads();
    if (t < 32) {
        float x = (t < 8) ? wred[t] : 0.f;
#pragma unroll
        for (int o = 4; o > 0; o >>= 1) x += __shfl_down_sync(0xffffffffu, x, o);
        if (t == 0) {
            g_dp[bx] = x;
            __threadfence();
            unsigned old = atomicAdd(&g_ctr, 1u);
            slast = (old == 1023u);
        }
    }
    __syncthreads();

    if (slast) {
        float v = g_lp[t] + g_lp[t + 256]
                + g_dp[t] + g_dp[t + 256] + g_dp[t + 512] + g_dp[t + 768];
#pragma unroll
        for (int o = 16; o > 0; o >>= 1) v += __shfl_down_sync(0xffffffffu, v, o);
        if ((t & 31) == 0) wred[t >> 5] = v;
        __syncthreads();
        if (t == 0) {
            float s = 0.f;
#pragma unroll
            for (int w = 0; w < 8; w++) s += wred[w];
            out[0] = s;
            g_ctr = 0;   // reset for next graph replay
        }
    }
}

// ---------------------------------------------------------------------------
extern "C" void kernel_launch(void* const* d_in, const int* in_sizes, int n_in,
                              void* d_out, int out_size) {
    const float* feat   = (const float*)d_in[0];
    const int*   labels = (const int*)d_in[1];
    const int*   dirs   = (const int*)d_in[2];
    float* out = (float*)d_out;

    const int smem = 14 * ROWB + 14 * 144 * 4;   // 72576 B
    cudaFuncSetAttribute(k_local, cudaFuncAttributeMaxDynamicSharedMemorySize, smem);

    k_norm<<<512, 256>>>(feat);
    k_local<<<512, 128, smem>>>(labels);
    k_dir<<<1024, 256>>>(labels, dirs, out);
}